// round 1
// baseline (speedup 1.0000x reference)
#include <cuda_runtime.h>
#include <math.h>

// ---------------------------------------------------------------------------
// Problem constants
// ---------------------------------------------------------------------------
#define DMODEL 1024
#define NHEAD  8
#define BQ     1024
#define NC     16384
#define HDIM   128      // DMODEL / NHEAD
#define FHID   64

// ---------------------------------------------------------------------------
// Device scratch (static globals; allocation APIs are forbidden)
// ---------------------------------------------------------------------------
__device__ float g_tmp   [NC * DMODEL];          // 64 MB  (proj hidden, q then k)
__device__ float g_qp    [BQ * DMODEL];          // 4 MB
__device__ float g_kp    [NC * DMODEL];          // 64 MB
__device__ float g_qh    [BQ * DMODEL];          // 4 MB
__device__ float g_kh    [NC * DMODEL];          // 64 MB
__device__ float g_dot   [(size_t)BQ * NC];      // 64 MB
__device__ float g_scores[(size_t)BQ * NHEAD * NC]; // 512 MB, layout [B][H][N]
__device__ float g_qsq   [BQ];
__device__ float g_ksq   [NC];
__device__ float g_rowmax[BQ * NHEAD];
__device__ float g_rowrcp[BQ * NHEAD];

// ---------------------------------------------------------------------------
// SGEMM tiles: 128x128x8, 256 threads, 8x8 per thread
// ---------------------------------------------------------------------------
#define BM 128
#define BN 128
#define BK 8
#define TM 8
#define TN 8

// C[M,N] = A[M,K] @ B[K,N] + bias[N]      (all row-major)
__global__ __launch_bounds__(256)
void gemm_nn(const float* __restrict__ A, const float* __restrict__ Bm,
             const float* __restrict__ bias, float* __restrict__ C,
             int K, int lda, int ldb, int ldc)
{
    __shared__ float As[BK][BM];
    __shared__ float Bs[BK][BN];
    const int tid = threadIdx.x;
    const int br = blockIdx.y * BM;
    const int bc = blockIdx.x * BN;

    const int arow = tid >> 1, acol = (tid & 1) * 4;   // 128 x 8 A tile
    const int brow = tid >> 5, bcol = (tid & 31) * 4;  // 8 x 128 B tile
    const int tr = (tid >> 4) * TM;
    const int tc = (tid & 15) * TN;

    float acc[TM][TN] = {};

    for (int k0 = 0; k0 < K; k0 += BK) {
        float4 a4 = *reinterpret_cast<const float4*>(&A[(size_t)(br + arow) * lda + k0 + acol]);
        As[acol + 0][arow] = a4.x; As[acol + 1][arow] = a4.y;
        As[acol + 2][arow] = a4.z; As[acol + 3][arow] = a4.w;
        *reinterpret_cast<float4*>(&Bs[brow][bcol]) =
            *reinterpret_cast<const float4*>(&Bm[(size_t)(k0 + brow) * ldb + bc + bcol]);
        __syncthreads();
#pragma unroll
        for (int k = 0; k < BK; ++k) {
            float ra[TM], rb[TN];
#pragma unroll
            for (int i = 0; i < TM; ++i) ra[i] = As[k][tr + i];
#pragma unroll
            for (int j = 0; j < TN; ++j) rb[j] = Bs[k][tc + j];
#pragma unroll
            for (int i = 0; i < TM; ++i)
#pragma unroll
                for (int j = 0; j < TN; ++j)
                    acc[i][j] = fmaf(ra[i], rb[j], acc[i][j]);
        }
        __syncthreads();
    }

#pragma unroll
    for (int i = 0; i < TM; ++i) {
#pragma unroll
        for (int j = 0; j < TN; j += 4) {
            float4 o;
            o.x = acc[i][j + 0] + bias[bc + tc + j + 0];
            o.y = acc[i][j + 1] + bias[bc + tc + j + 1];
            o.z = acc[i][j + 2] + bias[bc + tc + j + 2];
            o.w = acc[i][j + 3] + bias[bc + tc + j + 3];
            *reinterpret_cast<float4*>(&C[(size_t)(br + tr + i) * ldc + bc + tc + j]) = o;
        }
    }
}

// C[M,N] = alpha * A[M,K] @ B[N,K]^T      (row-major), batched over blockIdx.z
__global__ __launch_bounds__(256)
void gemm_nt(const float* __restrict__ A, const float* __restrict__ Bm,
             float* __restrict__ C,
             int K, int lda, int ldb, int ldc,
             int azs, int bzs, int czs, float alpha)
{
    __shared__ float As[BK][BM];
    __shared__ float Bs[BK][BN];
    const int tid = threadIdx.x;
    const int br = blockIdx.y * BM;
    const int bc = blockIdx.x * BN;
    A  += (size_t)blockIdx.z * azs;
    Bm += (size_t)blockIdx.z * bzs;
    C  += (size_t)blockIdx.z * czs;

    const int arow = tid >> 1, acol = (tid & 1) * 4;   // 128 x 8 tiles (both operands)
    const int tr = (tid >> 4) * TM;
    const int tc = (tid & 15) * TN;

    float acc[TM][TN] = {};

    for (int k0 = 0; k0 < K; k0 += BK) {
        float4 a4 = *reinterpret_cast<const float4*>(&A[(size_t)(br + arow) * lda + k0 + acol]);
        As[acol + 0][arow] = a4.x; As[acol + 1][arow] = a4.y;
        As[acol + 2][arow] = a4.z; As[acol + 3][arow] = a4.w;
        float4 b4 = *reinterpret_cast<const float4*>(&Bm[(size_t)(bc + arow) * ldb + k0 + acol]);
        Bs[acol + 0][arow] = b4.x; Bs[acol + 1][arow] = b4.y;
        Bs[acol + 2][arow] = b4.z; Bs[acol + 3][arow] = b4.w;
        __syncthreads();
#pragma unroll
        for (int k = 0; k < BK; ++k) {
            float ra[TM], rb[TN];
#pragma unroll
            for (int i = 0; i < TM; ++i) ra[i] = As[k][tr + i];
#pragma unroll
            for (int j = 0; j < TN; ++j) rb[j] = Bs[k][tc + j];
#pragma unroll
            for (int i = 0; i < TM; ++i)
#pragma unroll
                for (int j = 0; j < TN; ++j)
                    acc[i][j] = fmaf(ra[i], rb[j], acc[i][j]);
        }
        __syncthreads();
    }

#pragma unroll
    for (int i = 0; i < TM; ++i) {
#pragma unroll
        for (int j = 0; j < TN; j += 4) {
            float4 o;
            o.x = acc[i][j + 0] * alpha;
            o.y = acc[i][j + 1] * alpha;
            o.z = acc[i][j + 2] * alpha;
            o.w = acc[i][j + 3] * alpha;
            *reinterpret_cast<float4*>(&C[(size_t)(br + tr + i) * ldc + bc + tc + j]) = o;
        }
    }
}

// ---------------------------------------------------------------------------
// Fused LayerNorm + exact GELU over rows of length DMODEL (in-place).
// 256 threads, 4 elements each.
// ---------------------------------------------------------------------------
__global__ __launch_bounds__(256)
void ln_gelu_kernel(float* __restrict__ X,
                    const float* __restrict__ g, const float* __restrict__ be)
{
    const int row = blockIdx.x, tid = threadIdx.x;
    float* x = X + (size_t)row * DMODEL;
    float4 v = *reinterpret_cast<float4*>(&x[tid * 4]);
    float s  = v.x + v.y + v.z + v.w;
    float s2 = v.x * v.x + v.y * v.y + v.z * v.z + v.w * v.w;

    __shared__ float shs[32], shs2[32], bc[2];
#pragma unroll
    for (int o = 16; o > 0; o >>= 1) {
        s  += __shfl_xor_sync(0xffffffffu, s, o);
        s2 += __shfl_xor_sync(0xffffffffu, s2, o);
    }
    if ((tid & 31) == 0) { shs[tid >> 5] = s; shs2[tid >> 5] = s2; }
    __syncthreads();
    if (tid == 0) {
        float a = 0.f, b2 = 0.f;
        for (int i = 0; i < 8; ++i) { a += shs[i]; b2 += shs2[i]; }
        bc[0] = a  * (1.f / DMODEL);
        bc[1] = b2 * (1.f / DMODEL);
    }
    __syncthreads();
    const float mu  = bc[0];
    const float var = bc[1] - mu * mu;
    const float inv = rsqrtf(var + 1e-5f);

    float4 gg = *reinterpret_cast<const float4*>(&g[tid * 4]);
    float4 bb = *reinterpret_cast<const float4*>(&be[tid * 4]);

    float y;
    y = (v.x - mu) * inv * gg.x + bb.x;  v.x = 0.5f * y * (1.f + erff(y * 0.70710678118654752f));
    y = (v.y - mu) * inv * gg.y + bb.y;  v.y = 0.5f * y * (1.f + erff(y * 0.70710678118654752f));
    y = (v.z - mu) * inv * gg.z + bb.z;  v.z = 0.5f * y * (1.f + erff(y * 0.70710678118654752f));
    y = (v.w - mu) * inv * gg.w + bb.w;  v.w = 0.5f * y * (1.f + erff(y * 0.70710678118654752f));
    *reinterpret_cast<float4*>(&x[tid * 4]) = v;
}

// ---------------------------------------------------------------------------
// Row sum-of-squares: out[row] = sum(X[row,:]^2), row length DMODEL
// ---------------------------------------------------------------------------
__global__ __launch_bounds__(256)
void rowsq_kernel(const float* __restrict__ X, float* __restrict__ out)
{
    const int row = blockIdx.x, tid = threadIdx.x;
    const float* x = X + (size_t)row * DMODEL;
    float4 v = *reinterpret_cast<const float4*>(&x[tid * 4]);
    float s = v.x * v.x + v.y * v.y + v.z * v.z + v.w * v.w;
    __shared__ float sh[32];
#pragma unroll
    for (int o = 16; o > 0; o >>= 1) s += __shfl_xor_sync(0xffffffffu, s, o);
    if ((tid & 31) == 0) sh[tid >> 5] = s;
    __syncthreads();
    if (tid == 0) {
        float a = 0.f;
        for (int i = 0; i < 8; ++i) a += sh[i];
        out[row] = a;
    }
}

// ---------------------------------------------------------------------------
// Softmax stats per (b,h) row of scores: max and 1/sum(exp(s - max))
// ---------------------------------------------------------------------------
__global__ __launch_bounds__(256)
void softmax_stats_kernel(const float* __restrict__ S,
                          float* __restrict__ rmax, float* __restrict__ rrcp)
{
    const int row = blockIdx.x, tid = threadIdx.x;
    const float* s = S + (size_t)row * NC;
    __shared__ float sh[32], bc[1];

    float m = -INFINITY;
    for (int n = tid; n < NC; n += 256) m = fmaxf(m, s[n]);
#pragma unroll
    for (int o = 16; o > 0; o >>= 1) m = fmaxf(m, __shfl_xor_sync(0xffffffffu, m, o));
    if ((tid & 31) == 0) sh[tid >> 5] = m;
    __syncthreads();
    if (tid == 0) {
        float a = -INFINITY;
        for (int i = 0; i < 8; ++i) a = fmaxf(a, sh[i]);
        bc[0] = a;
    }
    __syncthreads();
    const float mx = bc[0];

    float sum = 0.f;
    for (int n = tid; n < NC; n += 256) sum += expf(s[n] - mx);
    __syncthreads();
#pragma unroll
    for (int o = 16; o > 0; o >>= 1) sum += __shfl_xor_sync(0xffffffffu, sum, o);
    if ((tid & 31) == 0) sh[tid >> 5] = sum;
    __syncthreads();
    if (tid == 0) {
        float a = 0.f;
        for (int i = 0; i < 8; ++i) a += sh[i];
        rmax[row] = mx;
        rrcp[row] = 1.f / a;
    }
}

// ---------------------------------------------------------------------------
// Fused epilogue: cosine / euclidean / learned similarity -> MLP -> sigmoid
// grid (NC/256, BQ), 256 threads; one (b,n) per thread.
// ---------------------------------------------------------------------------
__global__ __launch_bounds__(256)
void fuse_kernel(const float* __restrict__ dot, const float* __restrict__ scores,
                 const float* __restrict__ qsq, const float* __restrict__ ksq,
                 const float* __restrict__ rmax, const float* __restrict__ rrcp,
                 const float* __restrict__ temp,
                 const float* __restrict__ fw1, const float* __restrict__ fb1,
                 const float* __restrict__ fw2, const float* __restrict__ fb2,
                 float* __restrict__ out)
{
    __shared__ float w1[3][FHID], b1s[FHID], w2s[FHID];
    const int tid = threadIdx.x;
    if (tid < 3 * FHID) w1[tid / FHID][tid % FHID] = fw1[tid];
    if (tid < FHID) { b1s[tid] = fb1[tid]; w2s[tid] = fw2[tid]; }
    __syncthreads();

    const int b = blockIdx.y;
    const int n = blockIdx.x * 256 + tid;
    const float expT = expf(temp[0]);

    const float d  = dot[(size_t)b * NC + n];
    const float qs = qsq[b];
    const float ks = ksq[n];

    const float cs = d * rsqrtf(qs * ks) * expT;
    const float d2 = fmaxf(qs + ks - 2.f * d, 0.f);
    const float eu = 1.f / (1.f + sqrtf(d2));

    float ls = 0.f;
#pragma unroll
    for (int h = 0; h < NHEAD; ++h) {
        const int r = b * NHEAD + h;
        ls += expf(scores[(size_t)r * NC + n] - rmax[r]) * rrcp[r];
    }
    ls *= (1.f / NHEAD);

    float logit = fb2[0];
#pragma unroll
    for (int j = 0; j < FHID; ++j) {
        float hj = fmaf(cs, w1[0][j], fmaf(eu, w1[1][j], fmaf(ls, w1[2][j], b1s[j])));
        logit = fmaf(fmaxf(hj, 0.f), w2s[j], logit);
    }
    out[(size_t)b * NC + n] = 1.f / (1.f + expf(-logit));
}

// ---------------------------------------------------------------------------
// Host launcher
// ---------------------------------------------------------------------------
extern "C" void kernel_launch(void* const* d_in, const int* in_sizes, int n_in,
                              void* d_out, int out_size)
{
    const float* query = (const float*)d_in[0];
    const float* cand  = (const float*)d_in[1];
    const float* temp  = (const float*)d_in[2];
    const float* q_w1  = (const float*)d_in[3];
    const float* q_b1  = (const float*)d_in[4];
    const float* q_g   = (const float*)d_in[5];
    const float* q_be  = (const float*)d_in[6];
    const float* q_w2  = (const float*)d_in[7];
    const float* q_b2  = (const float*)d_in[8];
    const float* k_w1  = (const float*)d_in[9];
    const float* k_b1  = (const float*)d_in[10];
    const float* k_g   = (const float*)d_in[11];
    const float* k_be  = (const float*)d_in[12];
    const float* k_w2  = (const float*)d_in[13];
    const float* k_b2  = (const float*)d_in[14];
    const float* wq    = (const float*)d_in[15];
    const float* bq    = (const float*)d_in[16];
    const float* wk    = (const float*)d_in[17];
    const float* bk    = (const float*)d_in[18];
    const float* f_w1  = (const float*)d_in[19];
    const float* f_b1  = (const float*)d_in[20];
    const float* f_w2  = (const float*)d_in[21];
    const float* f_b2  = (const float*)d_in[22];
    float* out = (float*)d_out;

    float *tmp, *qp, *kp, *qh, *kh, *dotb, *sc, *qsq, *ksq, *rm, *rr;
    cudaGetSymbolAddress((void**)&tmp,  g_tmp);
    cudaGetSymbolAddress((void**)&qp,   g_qp);
    cudaGetSymbolAddress((void**)&kp,   g_kp);
    cudaGetSymbolAddress((void**)&qh,   g_qh);
    cudaGetSymbolAddress((void**)&kh,   g_kh);
    cudaGetSymbolAddress((void**)&dotb, g_dot);
    cudaGetSymbolAddress((void**)&sc,   g_scores);
    cudaGetSymbolAddress((void**)&qsq,  g_qsq);
    cudaGetSymbolAddress((void**)&ksq,  g_ksq);
    cudaGetSymbolAddress((void**)&rm,   g_rowmax);
    cudaGetSymbolAddress((void**)&rr,   g_rowrcp);

    const dim3 thr(256);
    const float inv_sqrt_hd = 0.08838834764831845f;  // 1/sqrt(128)

    // --- query projection: Linear -> LN -> GELU -> Linear ---
    gemm_nn<<<dim3(DMODEL / BN, BQ / BM), thr>>>(query, q_w1, q_b1, tmp,
                                                 DMODEL, DMODEL, DMODEL, DMODEL);
    ln_gelu_kernel<<<BQ, thr>>>(tmp, q_g, q_be);
    gemm_nn<<<dim3(DMODEL / BN, BQ / BM), thr>>>(tmp, q_w2, q_b2, qp,
                                                 DMODEL, DMODEL, DMODEL, DMODEL);

    // --- key projection ---
    gemm_nn<<<dim3(DMODEL / BN, NC / BM), thr>>>(cand, k_w1, k_b1, tmp,
                                                 DMODEL, DMODEL, DMODEL, DMODEL);
    ln_gelu_kernel<<<NC, thr>>>(tmp, k_g, k_be);
    gemm_nn<<<dim3(DMODEL / BN, NC / BM), thr>>>(tmp, k_w2, k_b2, kp,
                                                 DMODEL, DMODEL, DMODEL, DMODEL);

    // --- MHA head projections ---
    gemm_nn<<<dim3(DMODEL / BN, BQ / BM), thr>>>(qp, wq, bq, qh,
                                                 DMODEL, DMODEL, DMODEL, DMODEL);
    gemm_nn<<<dim3(DMODEL / BN, NC / BM), thr>>>(kp, wk, bk, kh,
                                                 DMODEL, DMODEL, DMODEL, DMODEL);

    // --- norms ---
    rowsq_kernel<<<BQ, thr>>>(qp, qsq);
    rowsq_kernel<<<NC, thr>>>(kp, ksq);

    // --- dot = qp @ kp^T ---
    gemm_nt<<<dim3(NC / BN, BQ / BM, 1), thr>>>(qp, kp, dotb,
                                                DMODEL, DMODEL, DMODEL, NC,
                                                0, 0, 0, 1.f);

    // --- per-head scores = (qh_h @ kh_h^T) / sqrt(HD), layout [B][H][N] ---
    gemm_nt<<<dim3(NC / BN, BQ / BM, NHEAD), thr>>>(qh, kh, sc,
                                                    HDIM, DMODEL, DMODEL, NHEAD * NC,
                                                    HDIM, HDIM, NC, inv_sqrt_hd);

    // --- softmax statistics per (b,h) ---
    softmax_stats_kernel<<<BQ * NHEAD, thr>>>(sc, rm, rr);

    // --- fused similarity + MLP + sigmoid ---
    fuse_kernel<<<dim3(NC / 256, BQ), thr>>>(dotb, sc, qsq, ksq, rm, rr, temp,
                                             f_w1, f_b1, f_w2, f_b2, out);
}

// round 3
// speedup vs baseline: 4.2521x; 4.2521x over previous
#include <cuda_runtime.h>
#include <cuda_fp16.h>
#include <math.h>
#include <stdint.h>

// ---------------------------------------------------------------------------
// Problem constants
// ---------------------------------------------------------------------------
#define DMODEL 1024
#define NHEAD  8
#define BQ     1024
#define NC     16384
#define HDIM   128
#define FHID   64

// GEMM tiling
#define BM   128
#define BN   128
#define BKH  32
#define APAD 8
#define BPAD 8

// ---------------------------------------------------------------------------
// Device scratch
// ---------------------------------------------------------------------------
__device__ float  g_tmp32[NC * DMODEL];
__device__ float  g_qp32 [BQ * DMODEL];
__device__ float  g_kp32 [NC * DMODEL];
__device__ float  g_dot  [(size_t)BQ * NC];
__device__ float  g_qsq  [BQ];
__device__ float  g_ksq  [NC];
__device__ float  g_rowmax[BQ * NHEAD];
__device__ float  g_rowrcp[BQ * NHEAD];

__device__ __half g_q16  [BQ * DMODEL];
__device__ __half g_c16  [NC * DMODEL];
__device__ __half g_tmp16[NC * DMODEL];
__device__ __half g_qp16 [BQ * DMODEL];
__device__ __half g_kp16 [NC * DMODEL];
__device__ __half g_qh16 [BQ * DMODEL];
__device__ __half g_kh16 [NC * DMODEL];
__device__ __half g_sc16 [(size_t)BQ * NHEAD * NC];
__device__ __half g_w16  [6 * DMODEL * DMODEL];

// ---------------------------------------------------------------------------
// PTX helpers (plain inline functions, no macros)
// ---------------------------------------------------------------------------
__device__ __forceinline__ void cp16(void* dst, const void* src)
{
    uint32_t d = (uint32_t)__cvta_generic_to_shared(dst);
    asm volatile("cp.async.cg.shared.global [%0], [%1], 16;\n" :: "r"(d), "l"(src));
}
__device__ __forceinline__ void cp_commit()
{
    asm volatile("cp.async.commit_group;\n");
}
__device__ __forceinline__ void cp_wait0()
{
    asm volatile("cp.async.wait_group 0;\n");
}
__device__ __forceinline__ void ldsm_x4(uint32_t& r0, uint32_t& r1, uint32_t& r2, uint32_t& r3,
                                        const void* p)
{
    uint32_t a = (uint32_t)__cvta_generic_to_shared(p);
    asm volatile("ldmatrix.sync.aligned.m8n8.x4.shared.b16 {%0,%1,%2,%3}, [%4];\n"
                 : "=r"(r0), "=r"(r1), "=r"(r2), "=r"(r3) : "r"(a));
}
__device__ __forceinline__ void ldsm_x4_t(uint32_t& r0, uint32_t& r1, uint32_t& r2, uint32_t& r3,
                                          const void* p)
{
    uint32_t a = (uint32_t)__cvta_generic_to_shared(p);
    asm volatile("ldmatrix.sync.aligned.m8n8.x4.trans.shared.b16 {%0,%1,%2,%3}, [%4];\n"
                 : "=r"(r0), "=r"(r1), "=r"(r2), "=r"(r3) : "r"(a));
}
__device__ __forceinline__ void mma16816(float* c,
                                         const uint32_t* a, const uint32_t* b)
{
    asm volatile("mma.sync.aligned.m16n8k16.row.col.f32.f16.f16.f32 "
                 "{%0,%1,%2,%3}, {%4,%5,%6,%7}, {%8,%9}, {%0,%1,%2,%3};\n"
                 : "+f"(c[0]), "+f"(c[1]), "+f"(c[2]), "+f"(c[3])
                 : "r"(a[0]), "r"(a[1]), "r"(a[2]), "r"(a[3]), "r"(b[0]), "r"(b[1]));
}

// ---------------------------------------------------------------------------
// HMMA GEMM, NN: C[M,N] = A16[M,K] @ B16[K,N] + bias
// wmode bit0: write fp32 C32, bit1: write fp16 C16
// ---------------------------------------------------------------------------
__device__ __forceinline__ void nn_load_stage(
    __half (*As)[BKH + APAD], __half (*Bs)[BN + BPAD],
    const __half* A, const __half* B, int lda, int ldb,
    int br, int bc, int k0, int tid)
{
    const int ar = tid >> 2,  ac  = (tid & 3)  * 8;
    const int brw = tid >> 4, bcc = (tid & 15) * 8;
    cp16(&As[ar][ac],        A + (size_t)(br + ar) * lda + k0 + ac);
    cp16(&As[ar + 64][ac],   A + (size_t)(br + ar + 64) * lda + k0 + ac);
    cp16(&Bs[brw][bcc],      B + (size_t)(k0 + brw) * ldb + bc + bcc);
    cp16(&Bs[brw + 16][bcc], B + (size_t)(k0 + brw + 16) * ldb + bc + bcc);
}

__global__ __launch_bounds__(256)
void gemm_nn16(const __half* __restrict__ A, const __half* __restrict__ B,
               const float* __restrict__ bias,
               float* __restrict__ C32, __half* __restrict__ C16,
               int K, int lda, int ldb, int ldc, int wmode)
{
    __shared__ __half As[2][BM][BKH + APAD];
    __shared__ __half Bs[2][BKH][BN + BPAD];

    const int tid  = threadIdx.x;
    const int br   = blockIdx.y * BM;
    const int bc   = blockIdx.x * BN;
    const int warp = tid >> 5, lane = tid & 31;
    const int wm   = (warp >> 2) * 64;
    const int wn   = (warp & 3) * 32;

    float acc[4][4][4];
#pragma unroll
    for (int i = 0; i < 4; ++i)
#pragma unroll
        for (int j = 0; j < 4; ++j)
#pragma unroll
            for (int r = 0; r < 4; ++r) acc[i][j][r] = 0.f;

    nn_load_stage(As[0], Bs[0], A, B, lda, ldb, br, bc, 0, tid);
    cp_commit();

    int buf = 0;
    for (int k0 = 0; k0 < K; k0 += BKH) {
        cp_wait0();
        __syncthreads();
        if (k0 + BKH < K) {
            nn_load_stage(As[buf ^ 1], Bs[buf ^ 1], A, B, lda, ldb, br, bc, k0 + BKH, tid);
            cp_commit();
        }

#pragma unroll
        for (int ks = 0; ks < 2; ++ks) {
            uint32_t a[4][4], b[4][2];
#pragma unroll
            for (int mt = 0; mt < 4; ++mt)
                ldsm_x4(a[mt][0], a[mt][1], a[mt][2], a[mt][3],
                        &As[buf][wm + mt * 16 + (lane & 15)][ks * 16 + (lane >> 4) * 8]);
#pragma unroll
            for (int nt2 = 0; nt2 < 2; ++nt2) {
                const int kk = ks * 16 + (lane & 7) + ((lane >> 3) & 1) * 8;
                const int nn = wn + nt2 * 16 + (lane >> 4) * 8;
                ldsm_x4_t(b[nt2 * 2][0], b[nt2 * 2][1], b[nt2 * 2 + 1][0], b[nt2 * 2 + 1][1],
                          &Bs[buf][kk][nn]);
            }
#pragma unroll
            for (int mt = 0; mt < 4; ++mt)
#pragma unroll
                for (int nt = 0; nt < 4; ++nt)
                    mma16816(acc[mt][nt], a[mt], b[nt]);
        }
        buf ^= 1;
    }

    const int g = lane >> 2, tig = lane & 3;
#pragma unroll
    for (int mt = 0; mt < 4; ++mt) {
#pragma unroll
        for (int nt = 0; nt < 4; ++nt) {
            const int row = br + wm + mt * 16 + g;
            const int col = bc + wn + nt * 8 + tig * 2;
            const float bx = bias[col], by = bias[col + 1];
            const float v00 = acc[mt][nt][0] + bx, v01 = acc[mt][nt][1] + by;
            const float v10 = acc[mt][nt][2] + bx, v11 = acc[mt][nt][3] + by;
            if (wmode & 1) {
                float2 u0 = make_float2(v00, v01);
                float2 u1 = make_float2(v10, v11);
                *reinterpret_cast<float2*>(&C32[(size_t)row * ldc + col]) = u0;
                *reinterpret_cast<float2*>(&C32[(size_t)(row + 8) * ldc + col]) = u1;
            }
            if (wmode & 2) {
                *reinterpret_cast<__half2*>(&C16[(size_t)row * ldc + col]) =
                    __floats2half2_rn(v00, v01);
                *reinterpret_cast<__half2*>(&C16[(size_t)(row + 8) * ldc + col]) =
                    __floats2half2_rn(v10, v11);
            }
        }
    }
}

// ---------------------------------------------------------------------------
// HMMA GEMM, NT: C[M,N] = alpha * A16[M,K] @ B16[N,K]^T, batched over z.
// f16out != 0 -> write fp16, else fp32.
// ---------------------------------------------------------------------------
__device__ __forceinline__ void nt_load_stage(
    __half (*As)[BKH + APAD], __half (*Bs)[BKH + APAD],
    const __half* A, const __half* B, int lda, int ldb,
    int br, int bc, int k0, int tid)
{
    const int ar = tid >> 2, ac = (tid & 3) * 8;
    cp16(&As[ar][ac],      A + (size_t)(br + ar) * lda + k0 + ac);
    cp16(&As[ar + 64][ac], A + (size_t)(br + ar + 64) * lda + k0 + ac);
    cp16(&Bs[ar][ac],      B + (size_t)(bc + ar) * ldb + k0 + ac);
    cp16(&Bs[ar + 64][ac], B + (size_t)(bc + ar + 64) * ldb + k0 + ac);
}

__global__ __launch_bounds__(256)
void gemm_nt16(const __half* __restrict__ A, const __half* __restrict__ B,
               float* __restrict__ C32, __half* __restrict__ C16,
               int K, int lda, int ldb, int ldc,
               int azs, int bzs, int czs, float alpha, int f16out)
{
    __shared__ __half As[2][BM][BKH + APAD];
    __shared__ __half Bs[2][BN][BKH + APAD];

    const int tid  = threadIdx.x;
    const int br   = blockIdx.y * BM;
    const int bc   = blockIdx.x * BN;
    const int warp = tid >> 5, lane = tid & 31;
    const int wm   = (warp >> 2) * 64;
    const int wn   = (warp & 3) * 32;
    A   += (size_t)blockIdx.z * azs;
    B   += (size_t)blockIdx.z * bzs;
    C32 += (size_t)blockIdx.z * czs;
    C16 += (size_t)blockIdx.z * czs;

    float acc[4][4][4];
#pragma unroll
    for (int i = 0; i < 4; ++i)
#pragma unroll
        for (int j = 0; j < 4; ++j)
#pragma unroll
            for (int r = 0; r < 4; ++r) acc[i][j][r] = 0.f;

    nt_load_stage(As[0], Bs[0], A, B, lda, ldb, br, bc, 0, tid);
    cp_commit();

    int buf = 0;
    for (int k0 = 0; k0 < K; k0 += BKH) {
        cp_wait0();
        __syncthreads();
        if (k0 + BKH < K) {
            nt_load_stage(As[buf ^ 1], Bs[buf ^ 1], A, B, lda, ldb, br, bc, k0 + BKH, tid);
            cp_commit();
        }

#pragma unroll
        for (int ks = 0; ks < 2; ++ks) {
            uint32_t a[4][4], b[4][2];
#pragma unroll
            for (int mt = 0; mt < 4; ++mt)
                ldsm_x4(a[mt][0], a[mt][1], a[mt][2], a[mt][3],
                        &As[buf][wm + mt * 16 + (lane & 15)][ks * 16 + (lane >> 4) * 8]);
#pragma unroll
            for (int nt2 = 0; nt2 < 2; ++nt2) {
                const int nn = wn + nt2 * 16 + (lane >> 4) * 8 + (lane & 7);
                const int kk = ks * 16 + ((lane >> 3) & 1) * 8;
                ldsm_x4(b[nt2 * 2][0], b[nt2 * 2][1], b[nt2 * 2 + 1][0], b[nt2 * 2 + 1][1],
                        &Bs[buf][nn][kk]);
            }
#pragma unroll
            for (int mt = 0; mt < 4; ++mt)
#pragma unroll
                for (int nt = 0; nt < 4; ++nt)
                    mma16816(acc[mt][nt], a[mt], b[nt]);
        }
        buf ^= 1;
    }

    const int g = lane >> 2, tig = lane & 3;
#pragma unroll
    for (int mt = 0; mt < 4; ++mt) {
#pragma unroll
        for (int nt = 0; nt < 4; ++nt) {
            const int row = br + wm + mt * 16 + g;
            const int col = bc + wn + nt * 8 + tig * 2;
            const float v00 = acc[mt][nt][0] * alpha, v01 = acc[mt][nt][1] * alpha;
            const float v10 = acc[mt][nt][2] * alpha, v11 = acc[mt][nt][3] * alpha;
            if (f16out) {
                *reinterpret_cast<__half2*>(&C16[(size_t)row * ldc + col]) =
                    __floats2half2_rn(v00, v01);
                *reinterpret_cast<__half2*>(&C16[(size_t)(row + 8) * ldc + col]) =
                    __floats2half2_rn(v10, v11);
            } else {
                float2 u0 = make_float2(v00, v01);
                float2 u1 = make_float2(v10, v11);
                *reinterpret_cast<float2*>(&C32[(size_t)row * ldc + col]) = u0;
                *reinterpret_cast<float2*>(&C32[(size_t)(row + 8) * ldc + col]) = u1;
            }
        }
    }
}

// ---------------------------------------------------------------------------
// float -> half conversion
// ---------------------------------------------------------------------------
__global__ __launch_bounds__(256)
void f2h_kernel(const float* __restrict__ s, __half* __restrict__ d, int n)
{
    int i = (blockIdx.x * 256 + threadIdx.x) * 4;
    if (i < n) {
        float4 v = *reinterpret_cast<const float4*>(s + i);
        *reinterpret_cast<__half2*>(d + i)     = __floats2half2_rn(v.x, v.y);
        *reinterpret_cast<__half2*>(d + i + 2) = __floats2half2_rn(v.z, v.w);
    }
}

// ---------------------------------------------------------------------------
// Fused LayerNorm + exact GELU, fp32 in -> fp16 out
// ---------------------------------------------------------------------------
__global__ __launch_bounds__(256)
void ln_gelu_kernel(const float* __restrict__ X, __half* __restrict__ Y,
                    const float* __restrict__ g, const float* __restrict__ be)
{
    const int row = blockIdx.x, tid = threadIdx.x;
    const float* x = X + (size_t)row * DMODEL;
    float4 v = *reinterpret_cast<const float4*>(&x[tid * 4]);
    float s  = v.x + v.y + v.z + v.w;
    float s2 = v.x * v.x + v.y * v.y + v.z * v.z + v.w * v.w;

    __shared__ float shs[32];
    __shared__ float shs2[32];
    __shared__ float bc[2];
#pragma unroll
    for (int o = 16; o > 0; o >>= 1) {
        s  += __shfl_xor_sync(0xffffffffu, s, o);
        s2 += __shfl_xor_sync(0xffffffffu, s2, o);
    }
    if ((tid & 31) == 0) { shs[tid >> 5] = s; shs2[tid >> 5] = s2; }
    __syncthreads();
    if (tid == 0) {
        float a = 0.f, b2 = 0.f;
        for (int i = 0; i < 8; ++i) { a += shs[i]; b2 += shs2[i]; }
        bc[0] = a  * (1.f / DMODEL);
        bc[1] = b2 * (1.f / DMODEL);
    }
    __syncthreads();
    const float mu  = bc[0];
    const float inv = rsqrtf(bc[1] - mu * mu + 1e-5f);

    float4 gg = *reinterpret_cast<const float4*>(&g[tid * 4]);
    float4 bb = *reinterpret_cast<const float4*>(&be[tid * 4]);

    float y, o0, o1, o2, o3;
    y = (v.x - mu) * inv * gg.x + bb.x;  o0 = 0.5f * y * (1.f + erff(y * 0.70710678118654752f));
    y = (v.y - mu) * inv * gg.y + bb.y;  o1 = 0.5f * y * (1.f + erff(y * 0.70710678118654752f));
    y = (v.z - mu) * inv * gg.z + bb.z;  o2 = 0.5f * y * (1.f + erff(y * 0.70710678118654752f));
    y = (v.w - mu) * inv * gg.w + bb.w;  o3 = 0.5f * y * (1.f + erff(y * 0.70710678118654752f));

    __half* yp = Y + (size_t)row * DMODEL + tid * 4;
    *reinterpret_cast<__half2*>(yp)     = __floats2half2_rn(o0, o1);
    *reinterpret_cast<__half2*>(yp + 2) = __floats2half2_rn(o2, o3);
}

// ---------------------------------------------------------------------------
// Row sum-of-squares (fp32 input)
// ---------------------------------------------------------------------------
__global__ __launch_bounds__(256)
void rowsq_kernel(const float* __restrict__ X, float* __restrict__ out)
{
    const int row = blockIdx.x, tid = threadIdx.x;
    const float* x = X + (size_t)row * DMODEL;
    float4 v = *reinterpret_cast<const float4*>(&x[tid * 4]);
    float s = v.x * v.x + v.y * v.y + v.z * v.z + v.w * v.w;
    __shared__ float sh[32];
#pragma unroll
    for (int o = 16; o > 0; o >>= 1) s += __shfl_xor_sync(0xffffffffu, s, o);
    if ((tid & 31) == 0) sh[tid >> 5] = s;
    __syncthreads();
    if (tid == 0) {
        float a = 0.f;
        for (int i = 0; i < 8; ++i) a += sh[i];
        out[row] = a;
    }
}

// ---------------------------------------------------------------------------
// Softmax stats per (b,h) row of fp16 scores: max and 1/sum(exp)
// ---------------------------------------------------------------------------
__global__ __launch_bounds__(256)
void softmax_stats_kernel(const __half* __restrict__ S,
                          float* __restrict__ rmax, float* __restrict__ rrcp)
{
    const int row = blockIdx.x, tid = threadIdx.x;
    const __half2* s2 = reinterpret_cast<const __half2*>(S + (size_t)row * NC);
    __shared__ float sh[32];
    __shared__ float bc[1];

    float m = -INFINITY;
    float2 vals[32];
#pragma unroll
    for (int i = 0; i < 32; ++i) {
        vals[i] = __half22float2(s2[tid + i * 256]);
        m = fmaxf(m, fmaxf(vals[i].x, vals[i].y));
    }
#pragma unroll
    for (int o = 16; o > 0; o >>= 1) m = fmaxf(m, __shfl_xor_sync(0xffffffffu, m, o));
    if ((tid & 31) == 0) sh[tid >> 5] = m;
    __syncthreads();
    if (tid == 0) {
        float a = -INFINITY;
        for (int i = 0; i < 8; ++i) a = fmaxf(a, sh[i]);
        bc[0] = a;
    }
    __syncthreads();
    const float mx = bc[0];

    float sum = 0.f;
#pragma unroll
    for (int i = 0; i < 32; ++i)
        sum += expf(vals[i].x - mx) + expf(vals[i].y - mx);
    __syncthreads();
#pragma unroll
    for (int o = 16; o > 0; o >>= 1) sum += __shfl_xor_sync(0xffffffffu, sum, o);
    if ((tid & 31) == 0) sh[tid >> 5] = sum;
    __syncthreads();
    if (tid == 0) {
        float a = 0.f;
        for (int i = 0; i < 8; ++i) a += sh[i];
        rmax[row] = mx;
        rrcp[row] = 1.f / a;
    }
}

// ---------------------------------------------------------------------------
// Fused epilogue: similarities -> MLP -> sigmoid
// ---------------------------------------------------------------------------
__global__ __launch_bounds__(256)
void fuse_kernel(const float* __restrict__ dot, const __half* __restrict__ scores,
                 const float* __restrict__ qsq, const float* __restrict__ ksq,
                 const float* __restrict__ rmax, const float* __restrict__ rrcp,
                 const float* __restrict__ temp,
                 const float* __restrict__ fw1, const float* __restrict__ fb1,
                 const float* __restrict__ fw2, const float* __restrict__ fb2,
                 float* __restrict__ out)
{
    __shared__ float w1[3][FHID];
    __shared__ float b1s[FHID];
    __shared__ float w2s[FHID];
    const int tid = threadIdx.x;
    if (tid < 3 * FHID) w1[tid / FHID][tid % FHID] = fw1[tid];
    if (tid < FHID) { b1s[tid] = fb1[tid]; w2s[tid] = fw2[tid]; }
    __syncthreads();

    const int b = blockIdx.y;
    const int n = blockIdx.x * 256 + tid;
    const float expT = expf(temp[0]);

    const float d  = dot[(size_t)b * NC + n];
    const float qs = qsq[b];
    const float ks = ksq[n];

    const float cs = d * rsqrtf(qs * ks) * expT;
    const float d2 = fmaxf(qs + ks - 2.f * d, 0.f);
    const float eu = 1.f / (1.f + sqrtf(d2));

    float ls = 0.f;
#pragma unroll
    for (int h = 0; h < NHEAD; ++h) {
        const int r = b * NHEAD + h;
        ls += expf(__half2float(scores[(size_t)r * NC + n]) - rmax[r]) * rrcp[r];
    }
    ls *= (1.f / NHEAD);

    float logit = fb2[0];
#pragma unroll
    for (int j = 0; j < FHID; ++j) {
        float hj = fmaf(cs, w1[0][j], fmaf(eu, w1[1][j], fmaf(ls, w1[2][j], b1s[j])));
        logit = fmaf(fmaxf(hj, 0.f), w2s[j], logit);
    }
    out[(size_t)b * NC + n] = 1.f / (1.f + expf(-logit));
}

// ---------------------------------------------------------------------------
// Host launcher
// ---------------------------------------------------------------------------
extern "C" void kernel_launch(void* const* d_in, const int* in_sizes, int n_in,
                              void* d_out, int out_size)
{
    const float* query = (const float*)d_in[0];
    const float* cand  = (const float*)d_in[1];
    const float* temp  = (const float*)d_in[2];
    const float* q_w1  = (const float*)d_in[3];
    const float* q_b1  = (const float*)d_in[4];
    const float* q_g   = (const float*)d_in[5];
    const float* q_be  = (const float*)d_in[6];
    const float* q_w2  = (const float*)d_in[7];
    const float* q_b2  = (const float*)d_in[8];
    const float* k_w1  = (const float*)d_in[9];
    const float* k_b1  = (const float*)d_in[10];
    const float* k_g   = (const float*)d_in[11];
    const float* k_be  = (const float*)d_in[12];
    const float* k_w2  = (const float*)d_in[13];
    const float* k_b2  = (const float*)d_in[14];
    const float* wq    = (const float*)d_in[15];
    const float* bq    = (const float*)d_in[16];
    const float* wk    = (const float*)d_in[17];
    const float* bk    = (const float*)d_in[18];
    const float* f_w1  = (const float*)d_in[19];
    const float* f_b1  = (const float*)d_in[20];
    const float* f_w2  = (const float*)d_in[21];
    const float* f_b2  = (const float*)d_in[22];
    float* out = (float*)d_out;

    float*  tmp32 = 0;
    float*  qp32  = 0;
    float*  kp32  = 0;
    float*  dotb  = 0;
    float*  qsq   = 0;
    float*  ksq   = 0;
    float*  rm    = 0;
    float*  rr    = 0;
    __half* q16   = 0;
    __half* c16   = 0;
    __half* tmp16 = 0;
    __half* qp16  = 0;
    __half* kp16  = 0;
    __half* qh16  = 0;
    __half* kh16  = 0;
    __half* sc16  = 0;
    __half* w16   = 0;

    cudaGetSymbolAddress((void**)&tmp32, g_tmp32);
    cudaGetSymbolAddress((void**)&qp32,  g_qp32);
    cudaGetSymbolAddress((void**)&kp32,  g_kp32);
    cudaGetSymbolAddress((void**)&dotb,  g_dot);
    cudaGetSymbolAddress((void**)&qsq,   g_qsq);
    cudaGetSymbolAddress((void**)&ksq,   g_ksq);
    cudaGetSymbolAddress((void**)&rm,    g_rowmax);
    cudaGetSymbolAddress((void**)&rr,    g_rowrcp);
    cudaGetSymbolAddress((void**)&q16,   g_q16);
    cudaGetSymbolAddress((void**)&c16,   g_c16);
    cudaGetSymbolAddress((void**)&tmp16, g_tmp16);
    cudaGetSymbolAddress((void**)&qp16,  g_qp16);
    cudaGetSymbolAddress((void**)&kp16,  g_kp16);
    cudaGetSymbolAddress((void**)&qh16,  g_qh16);
    cudaGetSymbolAddress((void**)&kh16,  g_kh16);
    cudaGetSymbolAddress((void**)&sc16,  g_sc16);
    cudaGetSymbolAddress((void**)&w16,   g_w16);

    const int WW = DMODEL * DMODEL;
    __half* qw1_16 = w16 + 0 * WW;
    __half* qw2_16 = w16 + 1 * WW;
    __half* kw1_16 = w16 + 2 * WW;
    __half* kw2_16 = w16 + 3 * WW;
    __half* wq_16  = w16 + 4 * WW;
    __half* wk_16  = w16 + 5 * WW;

    const dim3 thr(256);
    const dim3 gq(DMODEL / BN, BQ / BM);
    const dim3 gk(DMODEL / BN, NC / BM);
    const float inv_sqrt_hd = 0.08838834764831845f;  // 1/sqrt(128)

    // --- conversions to fp16 ---
    f2h_kernel<<<(BQ * DMODEL) / 1024, thr>>>(query, q16, BQ * DMODEL);
    f2h_kernel<<<(NC * DMODEL) / 1024, thr>>>(cand,  c16, NC * DMODEL);
    f2h_kernel<<<WW / 1024, thr>>>(q_w1, qw1_16, WW);
    f2h_kernel<<<WW / 1024, thr>>>(q_w2, qw2_16, WW);
    f2h_kernel<<<WW / 1024, thr>>>(k_w1, kw1_16, WW);
    f2h_kernel<<<WW / 1024, thr>>>(k_w2, kw2_16, WW);
    f2h_kernel<<<WW / 1024, thr>>>(wq,   wq_16,  WW);
    f2h_kernel<<<WW / 1024, thr>>>(wk,   wk_16,  WW);

    // --- query projection chain ---
    gemm_nn16<<<gq, thr>>>(q16, qw1_16, q_b1, tmp32, (__half*)0,
                           DMODEL, DMODEL, DMODEL, DMODEL, 1);
    ln_gelu_kernel<<<BQ, thr>>>(tmp32, tmp16, q_g, q_be);
    gemm_nn16<<<gq, thr>>>(tmp16, qw2_16, q_b2, qp32, qp16,
                           DMODEL, DMODEL, DMODEL, DMODEL, 3);

    // --- key projection chain ---
    gemm_nn16<<<gk, thr>>>(c16, kw1_16, k_b1, tmp32, (__half*)0,
                           DMODEL, DMODEL, DMODEL, DMODEL, 1);
    ln_gelu_kernel<<<NC, thr>>>(tmp32, tmp16, k_g, k_be);
    gemm_nn16<<<gk, thr>>>(tmp16, kw2_16, k_b2, kp32, kp16,
                           DMODEL, DMODEL, DMODEL, DMODEL, 3);

    // --- MHA head projections (fp16 out) ---
    gemm_nn16<<<gq, thr>>>(qp16, wq_16, bq, (float*)0, qh16,
                           DMODEL, DMODEL, DMODEL, DMODEL, 2);
    gemm_nn16<<<gk, thr>>>(kp16, wk_16, bk, (float*)0, kh16,
                           DMODEL, DMODEL, DMODEL, DMODEL, 2);

    // --- norms ---
    rowsq_kernel<<<BQ, thr>>>(qp32, qsq);
    rowsq_kernel<<<NC, thr>>>(kp32, ksq);

    // --- dot = qp @ kp^T (fp32 out) ---
    gemm_nt16<<<dim3(NC / BN, BQ / BM, 1), thr>>>(qp16, kp16, dotb, (__half*)0,
                                                  DMODEL, DMODEL, DMODEL, NC,
                                                  0, 0, 0, 1.f, 0);

    // --- per-head scores (fp16 out), layout [B][H][N] ---
    gemm_nt16<<<dim3(NC / BN, BQ / BM, NHEAD), thr>>>(qh16, kh16, (float*)0, sc16,
                                                      HDIM, DMODEL, DMODEL, NHEAD * NC,
                                                      HDIM, HDIM, NC, inv_sqrt_hd, 1);

    // --- softmax statistics per (b,h) ---
    softmax_stats_kernel<<<BQ * NHEAD, thr>>>(sc16, rm, rr);

    // --- fused similarity + MLP + sigmoid ---
    fuse_kernel<<<dim3(NC / 256, BQ), thr>>>(dotb, sc16, qsq, ksq, rm, rr, temp,
                                             f_w1, f_b1, f_w2, f_b2, out);
}